// round 12
// baseline (speedup 1.0000x reference)
#include <cuda_runtime.h>
#include <cuda_fp16.h>
#include <math.h>
#include <stdint.h>

#define HIDDEN 2048
#define NH 32
#define NKV 8
#define HD 64
#define BB 2
#define SEQ 2048
#define BSTOK (BB*SEQ)
#define QKVS 3072          // fused QKV row stride (halfs)
#define KOFF 2048
#define VOFF 2560

// ---------------------------------------------------------------------------
// Scratch
// ---------------------------------------------------------------------------
__device__ __half g_xh  [(size_t)BSTOK * HIDDEN];
__device__ __half g_QKVh[(size_t)BSTOK * QKVS];
__device__ __half g_Oh  [(size_t)BSTOK * HIDDEN];
__device__ __half g_Wqkv[(size_t)QKVS * HIDDEN];
__device__ __half g_WtO [(size_t)HIDDEN * HIDDEN];
__device__ float  g_cos[BSTOK * 32];
__device__ float  g_sin[BSTOK * 32];

// ---------------------------------------------------------------------------
// Helpers
// ---------------------------------------------------------------------------
__device__ __forceinline__ uint32_t smem_u32(const void* p) {
    uint32_t a;
    asm("{ .reg .u64 t; cvta.to.shared.u64 t, %1; cvt.u32.u64 %0, t; }"
        : "=r"(a) : "l"(p));
    return a;
}
__device__ __forceinline__ void cp16(uint32_t dst, const void* src) {
    asm volatile("cp.async.cg.shared.global [%0], [%1], 16;"
                 :: "r"(dst), "l"(src));
}
__device__ __forceinline__ void cp_commit() {
    asm volatile("cp.async.commit_group;");
}
__device__ __forceinline__ void ldsm4(uint32_t* r, uint32_t addr) {
    asm volatile("ldmatrix.sync.aligned.m8n8.x4.shared.b16 {%0,%1,%2,%3}, [%4];"
                 : "=r"(r[0]), "=r"(r[1]), "=r"(r[2]), "=r"(r[3]) : "r"(addr));
}
__device__ __forceinline__ void ldsm4t(uint32_t* r, uint32_t addr) {
    asm volatile("ldmatrix.sync.aligned.m8n8.x4.trans.shared.b16 {%0,%1,%2,%3}, [%4];"
                 : "=r"(r[0]), "=r"(r[1]), "=r"(r[2]), "=r"(r[3]) : "r"(addr));
}
__device__ __forceinline__ void mma16(float* c, const uint32_t* a,
                                      uint32_t b0, uint32_t b1) {
    asm volatile(
        "mma.sync.aligned.m16n8k16.row.col.f32.f16.f16.f32 "
        "{%0,%1,%2,%3}, {%4,%5,%6,%7}, {%8,%9}, {%0,%1,%2,%3};"
        : "+f"(c[0]), "+f"(c[1]), "+f"(c[2]), "+f"(c[3])
        : "r"(a[0]), "r"(a[1]), "r"(a[2]), "r"(a[3]), "r"(b0), "r"(b1));
}

// ---------------------------------------------------------------------------
// fp16 mma GEMM, cp.async 3-stage pipeline, K-chunk 64, 4-warp CTA,
// warp tile 64x64 (32 mma per 8 ldsm per k16-step). 2 CTAs/SM.
// C[M,N] = A[M,K] @ Bt[N,K]^T.  CTA tile 128x128.
// ---------------------------------------------------------------------------
#define KSTG 72
#define CHUNKB (128 * KSTG * 2)       // 18432 B per matrix per chunk
#define STAGEB (2 * CHUNKB)           // 36864
#define GEMM_SMEM_BYTES (3 * STAGEB)  // 110592

template<bool HOUT>
__global__ __launch_bounds__(128, 1) void gemm_h(
    const __half* __restrict__ A, const __half* __restrict__ Bt,
    void* __restrict__ Cv, int M, int N, int K) {
    extern __shared__ __half sh[];
    const uint32_t sbase = smem_u32(sh);
    const int tid  = threadIdx.x;
    const int wid  = tid >> 5;
    const int lane = tid & 31;
    const int gid  = lane >> 2;
    const int tid4 = lane & 3;
    const int wm   = wid & 1;         // 0..1 (64 M-rows)
    const int wn   = wid >> 1;        // 0..1 (64 N-cols)
    const int m0 = blockIdx.y * 128;
    const int n0 = blockIdx.x * 128;

    const int arow = (lane & 7) + ((lane >> 3) & 1) * 8;
    const int akof = (lane >> 4) * 8;
    const int brow = (lane & 7) + (lane >> 4) * 8;
    const int bkof = ((lane >> 3) & 1) * 8;

    // cooperative load: 1024 cp16 per matrix per chunk / 128 thr = 8 each
    int lrow[8], lv[8];
    #pragma unroll
    for (int i = 0; i < 8; i++) {
        int lin = i * 128 + tid;
        lrow[i] = lin >> 3;
        lv[i]   = lin & 7;
    }

    const __half* Ag = A  + (size_t)m0 * K;
    const __half* Bg = Bt + (size_t)n0 * K;
    const int nch = K / 64;

    float acc[4][8][4];
    #pragma unroll
    for (int mt = 0; mt < 4; mt++)
        #pragma unroll
        for (int nt = 0; nt < 8; nt++)
            #pragma unroll
            for (int c = 0; c < 4; c++) acc[mt][nt][c] = 0.f;

    auto issue = [&](int ch) {
        uint32_t As = sbase + (ch % 3) * STAGEB;
        uint32_t Bs = As + CHUNKB;
        const __half* Agc = Ag + ch * 64;
        const __half* Bgc = Bg + ch * 64;
        #pragma unroll
        for (int i = 0; i < 8; i++) {
            uint32_t so = (uint32_t)(lrow[i] * KSTG + lv[i] * 8) * 2;
            cp16(As + so, Agc + (size_t)lrow[i] * K + lv[i] * 8);
            cp16(Bs + so, Bgc + (size_t)lrow[i] * K + lv[i] * 8);
        }
        cp_commit();
    };

    issue(0); issue(1); issue(2);

    for (int ch = 0; ch < nch; ch++) {
        asm volatile("cp.async.wait_group 2;");
        __syncthreads();

        const uint32_t As = sbase + (ch % 3) * STAGEB;
        const uint32_t Bs = As + CHUNKB;
        #pragma unroll
        for (int ks = 0; ks < 4; ks++) {
            uint32_t af[4][4], bf[8][2];
            #pragma unroll
            for (int mt = 0; mt < 4; mt++)
                ldsm4(af[mt], As + ((wm * 64 + mt * 16 + arow) * KSTG
                                    + ks * 16 + akof) * 2);
            #pragma unroll
            for (int p = 0; p < 4; p++) {
                uint32_t b4[4];
                ldsm4(b4, Bs + ((wn * 64 + p * 16 + brow) * KSTG
                                + ks * 16 + bkof) * 2);
                bf[2 * p][0] = b4[0]; bf[2 * p][1] = b4[1];
                bf[2 * p + 1][0] = b4[2]; bf[2 * p + 1][1] = b4[3];
            }
            #pragma unroll
            for (int mt = 0; mt < 4; mt++)
                #pragma unroll
                for (int nt = 0; nt < 8; nt++)
                    mma16(acc[mt][nt], af[mt], bf[nt][0], bf[nt][1]);
        }
        __syncthreads();

        if (ch + 3 < nch) issue(ch + 3);
        else cp_commit();          // empty group keeps wait arithmetic exact
    }

    #pragma unroll
    for (int mt = 0; mt < 4; mt++) {
        const int r = m0 + wm * 64 + mt * 16 + gid;
        #pragma unroll
        for (int nt = 0; nt < 8; nt++) {
            const int col = n0 + wn * 64 + nt * 8 + tid4 * 2;
            if (HOUT) {
                __half* C = (__half*)Cv;
                *(__half2*)(C + (size_t)r * N + col) =
                    __floats2half2_rn(acc[mt][nt][0], acc[mt][nt][1]);
                *(__half2*)(C + (size_t)(r + 8) * N + col) =
                    __floats2half2_rn(acc[mt][nt][2], acc[mt][nt][3]);
            } else {
                float* C = (float*)Cv;
                float2 v0 = { acc[mt][nt][0], acc[mt][nt][1] };
                float2 v1 = { acc[mt][nt][2], acc[mt][nt][3] };
                *(float2*)(C + (size_t)r * N + col)       = v0;
                *(float2*)(C + (size_t)(r + 8) * N + col) = v1;
            }
        }
    }
}

// ---------------------------------------------------------------------------
// Small kernels
// ---------------------------------------------------------------------------
__global__ void convert_x(const float* __restrict__ X, __half* __restrict__ Xh,
                          int n4) {
    int idx = blockIdx.x * blockDim.x + threadIdx.x;
    if (idx >= n4) return;
    float4 v = ((const float4*)X)[idx];
    ((__half2*)Xh)[2 * idx]     = __floats2half2_rn(v.x, v.y);
    ((__half2*)Xh)[2 * idx + 1] = __floats2half2_rn(v.z, v.w);
}

__global__ void transpose_kh(const float* __restrict__ W, __half* __restrict__ Wt,
                             int R, int C) {
    __shared__ float tile[32][33];
    int c0 = blockIdx.x * 32, r0 = blockIdx.y * 32;
    int tx = threadIdx.x;
    for (int j = threadIdx.y; j < 32; j += 8)
        tile[j][tx] = W[(size_t)(r0 + j) * C + c0 + tx];
    __syncthreads();
    for (int j = threadIdx.y; j < 32; j += 8)
        Wt[(size_t)(c0 + j) * R + r0 + tx] = __float2half_rn(tile[tx][j]);
}

__global__ void rope_table(const int* __restrict__ pos) {
    int idx = blockIdx.x * blockDim.x + threadIdx.x;
    if (idx >= BSTOK * 32) return;
    int i = idx & 31, bs = idx >> 5;
    double inv_freq = exp(-(double)i * (9.210340371976184 / 32.0));
    double a = (double)pos[bs] * inv_freq;
    double s, c;
    sincos(a, &s, &c);
    g_cos[idx] = (float)c;
    g_sin[idx] = (float)s;
}

#define ROPE_Q (BSTOK * NH * 32)
#define ROPE_T (BSTOK * (NH + NKV) * 32)
__global__ void rope_all(__half* __restrict__ X) {
    int idx = blockIdx.x * blockDim.x + threadIdx.x;
    if (idx >= ROPE_T) return;
    int nheads, off, lidx;
    if (idx < ROPE_Q) { nheads = NH;  off = 0;    lidx = idx; }
    else              { nheads = NKV; off = KOFF; lidx = idx - ROPE_Q; }
    int i  = lidx & 31;
    int h  = (lidx >> 5) % nheads;
    int bs = lidx / (nheads * 32);
    float c  = g_cos[bs * 32 + i];
    float sn = g_sin[bs * 32 + i];
    __half* p = X + (size_t)bs * QKVS + off + h * HD;
    float x1 = __half2float(p[i]), x2 = __half2float(p[i + 32]);
    p[i]      = __float2half_rn(x1 * c - x2 * sn);
    p[i + 32] = __float2half_rn(x2 * c + x1 * sn);
}

// ---------------------------------------------------------------------------
// fp16 flash attention (unchanged from R9): 64-query CTA, cp.async K/V,
// heavy CTAs first.
// ---------------------------------------------------------------------------
#define KSTH 72
#define KVT (64 * KSTH)
#define FLASH_SMEM (5 * KVT * 2)   // 46080 B

__global__ __launch_bounds__(128, 1) void flash_h(
    const __half* __restrict__ QKV, __half* __restrict__ Oh) {
    extern __shared__ __half fsh[];
    const uint32_t fbase = smem_u32(fsh);
    __half* Ss = fsh + 4 * KVT;
    const uint32_t ssb = fbase + 4 * KVT * 2;

    const int tid  = threadIdx.x;
    const int warp = tid >> 5;
    const int lane = tid & 31;
    const int gid  = lane >> 2;
    const int tid4 = lane & 3;
    const int qb = gridDim.x - 1 - blockIdx.x;
    const int h = blockIdx.y, b = blockIdx.z;
    const int hkv = h >> 2;
    const int row0 = warp * 16;

    const int arow = (lane & 7) + ((lane >> 3) & 1) * 8;
    const int akof = (lane >> 4) * 8;
    const int brow = (lane & 7) + (lane >> 4) * 8;
    const int bkof = ((lane >> 3) & 1) * 8;
    const int vrow = (lane & 7) + ((lane >> 3) & 1) * 8;
    const int vkof = (lane >> 4) * 8;

    int klin[4], kv_[4];
    #pragma unroll
    for (int i = 0; i < 4; i++) {
        int lin = i * 128 + tid;
        klin[i] = lin >> 3;
        kv_[i]  = lin & 7;
    }
    auto issue = [&](int kt) {
        uint32_t Kb = fbase + (kt & 1) * 2 * KVT * 2;
        uint32_t Vb = Kb + KVT * 2;
        #pragma unroll
        for (int i = 0; i < 4; i++) {
            size_t rowb = (size_t)(b * SEQ + kt * 64 + klin[i]) * QKVS
                          + hkv * HD + kv_[i] * 8;
            uint32_t so = (uint32_t)(klin[i] * KSTH + kv_[i] * 8) * 2;
            cp16(Kb + so, QKV + rowb + KOFF);
            cp16(Vb + so, QKV + rowb + VOFF);
        }
        cp_commit();
    };

    #pragma unroll
    for (int j = 0; j < 4; j++) {
        int idx = j * 32 + lane;
        int r = idx >> 3, v = idx & 7;
        int token = b * SEQ + qb * 64 + row0 + r;
        *(uint4*)(Ss + (row0 + r) * KSTH + v * 8) =
            *(const uint4*)(QKV + (size_t)token * QKVS + h * HD + v * 8);
    }
    __syncwarp();
    uint32_t qf[4][4];
    #pragma unroll
    for (int ks = 0; ks < 4; ks++)
        ldsm4(qf[ks], ssb + ((row0 + arow) * KSTH + ks * 16 + akof) * 2);
    __syncwarp();

    float o[8][4];
    #pragma unroll
    for (int nt = 0; nt < 8; nt++)
        #pragma unroll
        for (int i = 0; i < 4; i++) o[nt][i] = 0.f;
    float m0 = -1e30f, m1 = -1e30f, l0 = 0.f, l1 = 0.f;

    issue(0);

    for (int kt = 0; kt <= qb; kt++) {
        if (kt < qb) { issue(kt + 1); asm volatile("cp.async.wait_group 1;"); }
        else         {                asm volatile("cp.async.wait_group 0;"); }
        __syncthreads();

        const uint32_t ksb = fbase + (kt & 1) * 2 * KVT * 2;
        const uint32_t vsb = ksb + KVT * 2;

        float c[8][4];
        #pragma unroll
        for (int nt = 0; nt < 8; nt++)
            #pragma unroll
            for (int i = 0; i < 4; i++) c[nt][i] = 0.f;
        #pragma unroll
        for (int ks = 0; ks < 4; ks++)
            #pragma unroll
            for (int p = 0; p < 4; p++) {
                uint32_t b4[4];
                ldsm4(b4, ksb + ((p * 16 + brow) * KSTH + ks * 16 + bkof) * 2);
                mma16(c[2 * p],     qf[ks], b4[0], b4[1]);
                mma16(c[2 * p + 1], qf[ks], b4[2], b4[3]);
            }

        #pragma unroll
        for (int nt = 0; nt < 8; nt++)
            #pragma unroll
            for (int i = 0; i < 4; i++) c[nt][i] *= 0.125f;
        if (kt == qb) {
            const int r0l = row0 + gid, r1l = row0 + gid + 8;
            #pragma unroll
            for (int nt = 0; nt < 8; nt++) {
                int cb = nt * 8 + 2 * tid4;
                if (cb     > r0l) c[nt][0] = -1e30f;
                if (cb + 1 > r0l) c[nt][1] = -1e30f;
                if (cb     > r1l) c[nt][2] = -1e30f;
                if (cb + 1 > r1l) c[nt][3] = -1e30f;
            }
        }

        float t0 = -1e30f, t1 = -1e30f;
        #pragma unroll
        for (int nt = 0; nt < 8; nt++) {
            t0 = fmaxf(t0, fmaxf(c[nt][0], c[nt][1]));
            t1 = fmaxf(t1, fmaxf(c[nt][2], c[nt][3]));
        }
        t0 = fmaxf(t0, __shfl_xor_sync(0xffffffffu, t0, 1));
        t0 = fmaxf(t0, __shfl_xor_sync(0xffffffffu, t0, 2));
        t1 = fmaxf(t1, __shfl_xor_sync(0xffffffffu, t1, 1));
        t1 = fmaxf(t1, __shfl_xor_sync(0xffffffffu, t1, 2));
        float m0n = fmaxf(m0, t0);
        float m1n = fmaxf(m1, t1);
        float cor0 = __expf(m0 - m0n);
        float cor1 = __expf(m1 - m1n);
        #pragma unroll
        for (int nt = 0; nt < 8; nt++) {
            o[nt][0] *= cor0; o[nt][1] *= cor0;
            o[nt][2] *= cor1; o[nt][3] *= cor1;
        }

        float s0 = 0.f, s1 = 0.f;
        #pragma unroll
        for (int nt = 0; nt < 8; nt++) {
            float p0 = __expf(c[nt][0] - m0n);
            float p1 = __expf(c[nt][1] - m0n);
            float p2 = __expf(c[nt][2] - m1n);
            float p3 = __expf(c[nt][3] - m1n);
            s0 += p0 + p1;
            s1 += p2 + p3;
            *(__half2*)(Ss + (row0 + gid)     * KSTH + nt * 8 + 2 * tid4) =
                __floats2half2_rn(p0, p1);
            *(__half2*)(Ss + (row0 + gid + 8) * KSTH + nt * 8 + 2 * tid4) =
                __floats2half2_rn(p2, p3);
        }
        s0 += __shfl_xor_sync(0xffffffffu, s0, 1);
        s0 += __shfl_xor_sync(0xffffffffu, s0, 2);
        s1 += __shfl_xor_sync(0xffffffffu, s1, 1);
        s1 += __shfl_xor_sync(0xffffffffu, s1, 2);
        l0 = l0 * cor0 + s0;
        l1 = l1 * cor1 + s1;
        m0 = m0n; m1 = m1n;
        __syncwarp();

        #pragma unroll
        for (int ks = 0; ks < 4; ks++) {
            uint32_t a4[4];
            ldsm4(a4, ssb + ((row0 + arow) * KSTH + ks * 16 + akof) * 2);
            #pragma unroll
            for (int p = 0; p < 4; p++) {
                uint32_t b4[4];
                ldsm4t(b4, vsb + ((ks * 16 + vrow) * KSTH + p * 16 + vkof) * 2);
                mma16(o[2 * p],     a4, b4[0], b4[1]);
                mma16(o[2 * p + 1], a4, b4[2], b4[3]);
            }
        }
        __syncthreads();
    }

    float inv0 = 1.f / l0, inv1 = 1.f / l1;
    int token0 = b * SEQ + qb * 64 + row0 + gid;
    __half* op0 = Oh + (size_t)token0 * HIDDEN + h * HD;
    __half* op1 = op0 + (size_t)8 * HIDDEN;
    #pragma unroll
    for (int nt = 0; nt < 8; nt++) {
        int col = nt * 8 + 2 * tid4;
        *(__half2*)(op0 + col) = __floats2half2_rn(o[nt][0] * inv0, o[nt][1] * inv0);
        *(__half2*)(op1 + col) = __floats2half2_rn(o[nt][2] * inv1, o[nt][3] * inv1);
    }
}

// ---------------------------------------------------------------------------
// Launch sequence
// ---------------------------------------------------------------------------
extern "C" void kernel_launch(void* const* d_in, const int* in_sizes, int n_in,
                              void* d_out, int out_size) {
    const float* x   = (const float*)d_in[0];
    const float* Wq  = (const float*)d_in[1];
    const float* Wk  = (const float*)d_in[2];
    const float* Wv  = (const float*)d_in[3];
    const float* Wo  = (const float*)d_in[4];
    const int*   pos = (const int*)d_in[5];
    float* out = (float*)d_out;

    __half *xh, *QKVh, *Oh, *Wqkv, *WtO;
    cudaGetSymbolAddress((void**)&xh,   g_xh);
    cudaGetSymbolAddress((void**)&QKVh, g_QKVh);
    cudaGetSymbolAddress((void**)&Oh,   g_Oh);
    cudaGetSymbolAddress((void**)&Wqkv, g_Wqkv);
    cudaGetSymbolAddress((void**)&WtO,  g_WtO);

    cudaFuncSetAttribute(gemm_h<true>,  cudaFuncAttributeMaxDynamicSharedMemorySize, GEMM_SMEM_BYTES);
    cudaFuncSetAttribute(gemm_h<false>, cudaFuncAttributeMaxDynamicSharedMemorySize, GEMM_SMEM_BYTES);
    cudaFuncSetAttribute(flash_h,       cudaFuncAttributeMaxDynamicSharedMemorySize, FLASH_SMEM);

    const int M = BSTOK;        // 4096
    dim3 tb(32, 8);

    convert_x<<<(BSTOK * HIDDEN / 4 + 255) / 256, 256>>>(x, xh, BSTOK * HIDDEN / 4);
    transpose_kh<<<dim3(HIDDEN / 32, HIDDEN / 32), tb>>>(Wq, Wqkv, HIDDEN, HIDDEN);
    transpose_kh<<<dim3((NKV * HD) / 32, HIDDEN / 32), tb>>>(
        Wk, Wqkv + (size_t)KOFF * HIDDEN, HIDDEN, NKV * HD);
    transpose_kh<<<dim3((NKV * HD) / 32, HIDDEN / 32), tb>>>(
        Wv, Wqkv + (size_t)VOFF * HIDDEN, HIDDEN, NKV * HD);
    rope_table<<<(BSTOK * 32 + 255) / 256, 256>>>(pos);

    // fused QKV projection (4-warp CTAs, warp tile 64x64)
    gemm_h<true><<<dim3(QKVS / 128, M / 128), 128, GEMM_SMEM_BYTES>>>(
        xh, Wqkv, QKVh, M, QKVS, HIDDEN);

    rope_all<<<(ROPE_T + 255) / 256, 256>>>(QKVh);

    flash_h<<<dim3(SEQ / 64, NH, BB), 128, FLASH_SMEM>>>(QKVh, Oh);

    transpose_kh<<<dim3(HIDDEN / 32, HIDDEN / 32), tb>>>(Wo, WtO, HIDDEN, HIDDEN);
    gemm_h<false><<<dim3(HIDDEN / 128, M / 128), 128, GEMM_SMEM_BYTES>>>(
        Oh, WtO, out, M, HIDDEN, HIDDEN);
}

// round 14
// speedup vs baseline: 1.3822x; 1.3822x over previous
#include <cuda_runtime.h>
#include <cuda_fp16.h>
#include <math.h>
#include <stdint.h>

#define HIDDEN 2048
#define NH 32
#define NKV 8
#define HD 64
#define BB 2
#define SEQ 2048
#define BSTOK (BB*SEQ)
#define QKVS 3072          // fused QKV row stride (halfs)
#define KOFF 2048
#define VOFF 2560

// ---------------------------------------------------------------------------
// Scratch
// ---------------------------------------------------------------------------
__device__ __half g_xh  [(size_t)BSTOK * HIDDEN];
__device__ __half g_QKVh[(size_t)BSTOK * QKVS];
__device__ __half g_Oh  [(size_t)BSTOK * HIDDEN];
__device__ __half g_Wqkv[(size_t)QKVS * HIDDEN];
__device__ __half g_WtO [(size_t)HIDDEN * HIDDEN];
__device__ float  g_cos[BSTOK * 32];
__device__ float  g_sin[BSTOK * 32];

// ---------------------------------------------------------------------------
// Helpers
// ---------------------------------------------------------------------------
__device__ __forceinline__ uint32_t smem_u32(const void* p) {
    uint32_t a;
    asm("{ .reg .u64 t; cvta.to.shared.u64 t, %1; cvt.u32.u64 %0, t; }"
        : "=r"(a) : "l"(p));
    return a;
}
__device__ __forceinline__ void cp16(uint32_t dst, const void* src) {
    asm volatile("cp.async.cg.shared.global [%0], [%1], 16;"
                 :: "r"(dst), "l"(src));
}
__device__ __forceinline__ void cp_commit() {
    asm volatile("cp.async.commit_group;");
}
__device__ __forceinline__ void ldsm4(uint32_t* r, uint32_t addr) {
    asm volatile("ldmatrix.sync.aligned.m8n8.x4.shared.b16 {%0,%1,%2,%3}, [%4];"
                 : "=r"(r[0]), "=r"(r[1]), "=r"(r[2]), "=r"(r[3]) : "r"(addr));
}
__device__ __forceinline__ void ldsm4t(uint32_t* r, uint32_t addr) {
    asm volatile("ldmatrix.sync.aligned.m8n8.x4.trans.shared.b16 {%0,%1,%2,%3}, [%4];"
                 : "=r"(r[0]), "=r"(r[1]), "=r"(r[2]), "=r"(r[3]) : "r"(addr));
}
__device__ __forceinline__ void mma16(float* c, const uint32_t* a,
                                      uint32_t b0, uint32_t b1) {
    asm volatile(
        "mma.sync.aligned.m16n8k16.row.col.f32.f16.f16.f32 "
        "{%0,%1,%2,%3}, {%4,%5,%6,%7}, {%8,%9}, {%0,%1,%2,%3};"
        : "+f"(c[0]), "+f"(c[1]), "+f"(c[2]), "+f"(c[3])
        : "r"(a[0]), "r"(a[1]), "r"(a[2]), "r"(a[3]), "r"(b0), "r"(b1));
}

// ---------------------------------------------------------------------------
// fp16 mma GEMM, cp.async 3-stage pipeline, K-chunk 64, 8-warp CTA,
// warp grid 4M x 2N (warp tile 32x64 -> one head per warp N-span).
// Optional fused RoPE in the epilogue (QKV GEMM: Q and K regions).
// C[M,N] = A[M,K] @ Bt[N,K]^T.  CTA tile 128x128.
// ---------------------------------------------------------------------------
#define KSTG 72
#define CHUNKB (128 * KSTG * 2)       // 18432 B per matrix per chunk
#define STAGEB (2 * CHUNKB)           // 36864
#define GEMM_SMEM_BYTES (3 * STAGEB)  // 110592

template<bool HOUT, bool ROPE>
__global__ __launch_bounds__(256, 1) void gemm_h(
    const __half* __restrict__ A, const __half* __restrict__ Bt,
    void* __restrict__ Cv, int M, int N, int K) {
    extern __shared__ __half sh[];
    const uint32_t sbase = smem_u32(sh);
    const int tid  = threadIdx.x;
    const int wid  = tid >> 5;
    const int lane = tid & 31;
    const int gid  = lane >> 2;
    const int tid4 = lane & 3;
    const int wm   = wid & 3;         // 0..3 (32 M-rows each)
    const int wn   = wid >> 2;        // 0..1 (64 N-cols each)
    const int m0 = blockIdx.y * 128;
    const int n0 = blockIdx.x * 128;

    const int arow = (lane & 7) + ((lane >> 3) & 1) * 8;
    const int akof = (lane >> 4) * 8;
    const int brow = (lane & 7) + (lane >> 4) * 8;
    const int bkof = ((lane >> 3) & 1) * 8;

    // cooperative load: 1024 cp16 per matrix per chunk / 256 thr = 4 each
    int lrow[4], lv[4];
    #pragma unroll
    for (int i = 0; i < 4; i++) {
        int lin = i * 256 + tid;
        lrow[i] = lin >> 3;
        lv[i]   = lin & 7;
    }

    const __half* Ag = A  + (size_t)m0 * K;
    const __half* Bg = Bt + (size_t)n0 * K;
    const int nch = K / 64;

    float acc[2][8][4];
    #pragma unroll
    for (int mt = 0; mt < 2; mt++)
        #pragma unroll
        for (int nt = 0; nt < 8; nt++)
            #pragma unroll
            for (int c = 0; c < 4; c++) acc[mt][nt][c] = 0.f;

    auto issue = [&](int ch) {
        uint32_t As = sbase + (ch % 3) * STAGEB;
        uint32_t Bs = As + CHUNKB;
        const __half* Agc = Ag + ch * 64;
        const __half* Bgc = Bg + ch * 64;
        #pragma unroll
        for (int i = 0; i < 4; i++) {
            uint32_t so = (uint32_t)(lrow[i] * KSTG + lv[i] * 8) * 2;
            cp16(As + so, Agc + (size_t)lrow[i] * K + lv[i] * 8);
            cp16(Bs + so, Bgc + (size_t)lrow[i] * K + lv[i] * 8);
        }
        cp_commit();
    };

    issue(0); issue(1); issue(2);

    for (int ch = 0; ch < nch; ch++) {
        asm volatile("cp.async.wait_group 2;");
        __syncthreads();

        const uint32_t As = sbase + (ch % 3) * STAGEB;
        const uint32_t Bs = As + CHUNKB;
        #pragma unroll
        for (int ks = 0; ks < 4; ks++) {
            uint32_t af[2][4], bf[8][2];
            #pragma unroll
            for (int mt = 0; mt < 2; mt++)
                ldsm4(af[mt], As + ((wm * 32 + mt * 16 + arow) * KSTG
                                    + ks * 16 + akof) * 2);
            #pragma unroll
            for (int p = 0; p < 4; p++) {
                uint32_t b4[4];
                ldsm4(b4, Bs + ((wn * 64 + p * 16 + brow) * KSTG
                                + ks * 16 + bkof) * 2);
                bf[2 * p][0] = b4[0]; bf[2 * p][1] = b4[1];
                bf[2 * p + 1][0] = b4[2]; bf[2 * p + 1][1] = b4[3];
            }
            #pragma unroll
            for (int mt = 0; mt < 2; mt++)
                #pragma unroll
                for (int nt = 0; nt < 8; nt++)
                    mma16(acc[mt][nt], af[mt], bf[nt][0], bf[nt][1]);
        }
        __syncthreads();

        if (ch + 3 < nch) issue(ch + 3);
        else cp_commit();          // empty group keeps wait arithmetic exact
    }

    // Epilogue. Warp N-span = 64 = one head; local col i = nt*8 + tid4*2,
    // pairs (i, i+32) live in acc[.][nt] / acc[.][nt+4].
    const bool do_rope = ROPE && (n0 < VOFF);
    #pragma unroll
    for (int mt = 0; mt < 2; mt++) {
        const int r = m0 + wm * 32 + mt * 16 + gid;     // rows r, r+8
        if (do_rope) {
            #pragma unroll
            for (int nt = 0; nt < 4; nt++) {
                const int i = nt * 8 + tid4 * 2;
                float2 c0 = *(const float2*)&g_cos[(size_t)r * 32 + i];
                float2 s0 = *(const float2*)&g_sin[(size_t)r * 32 + i];
                float2 c1 = *(const float2*)&g_cos[(size_t)(r + 8) * 32 + i];
                float2 s1 = *(const float2*)&g_sin[(size_t)(r + 8) * 32 + i];
                float x1, x2;
                x1 = acc[mt][nt][0]; x2 = acc[mt][nt + 4][0];
                acc[mt][nt][0]     = x1 * c0.x - x2 * s0.x;
                acc[mt][nt + 4][0] = x2 * c0.x + x1 * s0.x;
                x1 = acc[mt][nt][1]; x2 = acc[mt][nt + 4][1];
                acc[mt][nt][1]     = x1 * c0.y - x2 * s0.y;
                acc[mt][nt + 4][1] = x2 * c0.y + x1 * s0.y;
                x1 = acc[mt][nt][2]; x2 = acc[mt][nt + 4][2];
                acc[mt][nt][2]     = x1 * c1.x - x2 * s1.x;
                acc[mt][nt + 4][2] = x2 * c1.x + x1 * s1.x;
                x1 = acc[mt][nt][3]; x2 = acc[mt][nt + 4][3];
                acc[mt][nt][3]     = x1 * c1.y - x2 * s1.y;
                acc[mt][nt + 4][3] = x2 * c1.y + x1 * s1.y;
            }
        }
        #pragma unroll
        for (int nt = 0; nt < 8; nt++) {
            const int col = n0 + wn * 64 + nt * 8 + tid4 * 2;
            if (HOUT) {
                __half* C = (__half*)Cv;
                *(__half2*)(C + (size_t)r * N + col) =
                    __floats2half2_rn(acc[mt][nt][0], acc[mt][nt][1]);
                *(__half2*)(C + (size_t)(r + 8) * N + col) =
                    __floats2half2_rn(acc[mt][nt][2], acc[mt][nt][3]);
            } else {
                float* C = (float*)Cv;
                float2 v0 = { acc[mt][nt][0], acc[mt][nt][1] };
                float2 v1 = { acc[mt][nt][2], acc[mt][nt][3] };
                *(float2*)(C + (size_t)r * N + col)       = v0;
                *(float2*)(C + (size_t)(r + 8) * N + col) = v1;
            }
        }
    }
}

// ---------------------------------------------------------------------------
// Small kernels
// ---------------------------------------------------------------------------
__global__ void convert_x(const float* __restrict__ X, __half* __restrict__ Xh,
                          int n4) {
    int idx = blockIdx.x * blockDim.x + threadIdx.x;
    if (idx >= n4) return;
    float4 v = ((const float4*)X)[idx];
    ((__half2*)Xh)[2 * idx]     = __floats2half2_rn(v.x, v.y);
    ((__half2*)Xh)[2 * idx + 1] = __floats2half2_rn(v.z, v.w);
}

__global__ void transpose_kh(const float* __restrict__ W, __half* __restrict__ Wt,
                             int R, int C) {
    __shared__ float tile[32][33];
    int c0 = blockIdx.x * 32, r0 = blockIdx.y * 32;
    int tx = threadIdx.x;
    for (int j = threadIdx.y; j < 32; j += 8)
        tile[j][tx] = W[(size_t)(r0 + j) * C + c0 + tx];
    __syncthreads();
    for (int j = threadIdx.y; j < 32; j += 8)
        Wt[(size_t)(c0 + j) * R + r0 + tx] = __float2half_rn(tile[tx][j]);
}

__global__ void rope_table(const int* __restrict__ pos) {
    int idx = blockIdx.x * blockDim.x + threadIdx.x;
    if (idx >= BSTOK * 32) return;
    int i = idx & 31, bs = idx >> 5;
    double inv_freq = exp(-(double)i * (9.210340371976184 / 32.0));
    double a = (double)pos[bs] * inv_freq;
    double s, c;
    sincos(a, &s, &c);
    g_cos[idx] = (float)c;
    g_sin[idx] = (float)s;
}

// ---------------------------------------------------------------------------
// fp16 flash attention (unchanged): 64-query CTA, cp.async K/V,
// heavy CTAs first.
// ---------------------------------------------------------------------------
#define KSTH 72
#define KVT (64 * KSTH)
#define FLASH_SMEM (5 * KVT * 2)   // 46080 B

__global__ __launch_bounds__(128, 1) void flash_h(
    const __half* __restrict__ QKV, __half* __restrict__ Oh) {
    extern __shared__ __half fsh[];
    const uint32_t fbase = smem_u32(fsh);
    __half* Ss = fsh + 4 * KVT;
    const uint32_t ssb = fbase + 4 * KVT * 2;

    const int tid  = threadIdx.x;
    const int warp = tid >> 5;
    const int lane = tid & 31;
    const int gid  = lane >> 2;
    const int tid4 = lane & 3;
    const int qb = gridDim.x - 1 - blockIdx.x;
    const int h = blockIdx.y, b = blockIdx.z;
    const int hkv = h >> 2;
    const int row0 = warp * 16;

    const int arow = (lane & 7) + ((lane >> 3) & 1) * 8;
    const int akof = (lane >> 4) * 8;
    const int brow = (lane & 7) + (lane >> 4) * 8;
    const int bkof = ((lane >> 3) & 1) * 8;
    const int vrow = (lane & 7) + ((lane >> 3) & 1) * 8;
    const int vkof = (lane >> 4) * 8;

    int klin[4], kv_[4];
    #pragma unroll
    for (int i = 0; i < 4; i++) {
        int lin = i * 128 + tid;
        klin[i] = lin >> 3;
        kv_[i]  = lin & 7;
    }
    auto issue = [&](int kt) {
        uint32_t Kb = fbase + (kt & 1) * 2 * KVT * 2;
        uint32_t Vb = Kb + KVT * 2;
        #pragma unroll
        for (int i = 0; i < 4; i++) {
            size_t rowb = (size_t)(b * SEQ + kt * 64 + klin[i]) * QKVS
                          + hkv * HD + kv_[i] * 8;
            uint32_t so = (uint32_t)(klin[i] * KSTH + kv_[i] * 8) * 2;
            cp16(Kb + so, QKV + rowb + KOFF);
            cp16(Vb + so, QKV + rowb + VOFF);
        }
        cp_commit();
    };

    #pragma unroll
    for (int j = 0; j < 4; j++) {
        int idx = j * 32 + lane;
        int r = idx >> 3, v = idx & 7;
        int token = b * SEQ + qb * 64 + row0 + r;
        *(uint4*)(Ss + (row0 + r) * KSTH + v * 8) =
            *(const uint4*)(QKV + (size_t)token * QKVS + h * HD + v * 8);
    }
    __syncwarp();
    uint32_t qf[4][4];
    #pragma unroll
    for (int ks = 0; ks < 4; ks++)
        ldsm4(qf[ks], ssb + ((row0 + arow) * KSTH + ks * 16 + akof) * 2);
    __syncwarp();

    float o[8][4];
    #pragma unroll
    for (int nt = 0; nt < 8; nt++)
        #pragma unroll
        for (int i = 0; i < 4; i++) o[nt][i] = 0.f;
    float m0 = -1e30f, m1 = -1e30f, l0 = 0.f, l1 = 0.f;

    issue(0);

    for (int kt = 0; kt <= qb; kt++) {
        if (kt < qb) { issue(kt + 1); asm volatile("cp.async.wait_group 1;"); }
        else         {                asm volatile("cp.async.wait_group 0;"); }
        __syncthreads();

        const uint32_t ksb = fbase + (kt & 1) * 2 * KVT * 2;
        const uint32_t vsb = ksb + KVT * 2;

        float c[8][4];
        #pragma unroll
        for (int nt = 0; nt < 8; nt++)
            #pragma unroll
            for (int i = 0; i < 4; i++) c[nt][i] = 0.f;
        #pragma unroll
        for (int ks = 0; ks < 4; ks++)
            #pragma unroll
            for (int p = 0; p < 4; p++) {
                uint32_t b4[4];
                ldsm4(b4, ksb + ((p * 16 + brow) * KSTH + ks * 16 + bkof) * 2);
                mma16(c[2 * p],     qf[ks], b4[0], b4[1]);
                mma16(c[2 * p + 1], qf[ks], b4[2], b4[3]);
            }

        #pragma unroll
        for (int nt = 0; nt < 8; nt++)
            #pragma unroll
            for (int i = 0; i < 4; i++) c[nt][i] *= 0.125f;
        if (kt == qb) {
            const int r0l = row0 + gid, r1l = row0 + gid + 8;
            #pragma unroll
            for (int nt = 0; nt < 8; nt++) {
                int cb = nt * 8 + 2 * tid4;
                if (cb     > r0l) c[nt][0] = -1e30f;
                if (cb + 1 > r0l) c[nt][1] = -1e30f;
                if (cb     > r1l) c[nt][2] = -1e30f;
                if (cb + 1 > r1l) c[nt][3] = -1e30f;
            }
        }

        float t0 = -1e30f, t1 = -1e30f;
        #pragma unroll
        for (int nt = 0; nt < 8; nt++) {
            t0 = fmaxf(t0, fmaxf(c[nt][0], c[nt][1]));
            t1 = fmaxf(t1, fmaxf(c[nt][2], c[nt][3]));
        }
        t0 = fmaxf(t0, __shfl_xor_sync(0xffffffffu, t0, 1));
        t0 = fmaxf(t0, __shfl_xor_sync(0xffffffffu, t0, 2));
        t1 = fmaxf(t1, __shfl_xor_sync(0xffffffffu, t1, 1));
        t1 = fmaxf(t1, __shfl_xor_sync(0xffffffffu, t1, 2));
        float m0n = fmaxf(m0, t0);
        float m1n = fmaxf(m1, t1);
        float cor0 = __expf(m0 - m0n);
        float cor1 = __expf(m1 - m1n);
        #pragma unroll
        for (int nt = 0; nt < 8; nt++) {
            o[nt][0] *= cor0; o[nt][1] *= cor0;
            o[nt][2] *= cor1; o[nt][3] *= cor1;
        }

        float s0 = 0.f, s1 = 0.f;
        #pragma unroll
        for (int nt = 0; nt < 8; nt++) {
            float p0 = __expf(c[nt][0] - m0n);
            float p1 = __expf(c[nt][1] - m0n);
            float p2 = __expf(c[nt][2] - m1n);
            float p3 = __expf(c[nt][3] - m1n);
            s0 += p0 + p1;
            s1 += p2 + p3;
            *(__half2*)(Ss + (row0 + gid)     * KSTH + nt * 8 + 2 * tid4) =
                __floats2half2_rn(p0, p1);
            *(__half2*)(Ss + (row0 + gid + 8) * KSTH + nt * 8 + 2 * tid4) =
                __floats2half2_rn(p2, p3);
        }
        s0 += __shfl_xor_sync(0xffffffffu, s0, 1);
        s0 += __shfl_xor_sync(0xffffffffu, s0, 2);
        s1 += __shfl_xor_sync(0xffffffffu, s1, 1);
        s1 += __shfl_xor_sync(0xffffffffu, s1, 2);
        l0 = l0 * cor0 + s0;
        l1 = l1 * cor1 + s1;
        m0 = m0n; m1 = m1n;
        __syncwarp();

        #pragma unroll
        for (int ks = 0; ks < 4; ks++) {
            uint32_t a4[4];
            ldsm4(a4, ssb + ((row0 + arow) * KSTH + ks * 16 + akof) * 2);
            #pragma unroll
            for (int p = 0; p < 4; p++) {
                uint32_t b4[4];
                ldsm4t(b4, vsb + ((ks * 16 + vrow) * KSTH + p * 16 + vkof) * 2);
                mma16(o[2 * p],     a4, b4[0], b4[1]);
                mma16(o[2 * p + 1], a4, b4[2], b4[3]);
            }
        }
        __syncthreads();
    }

    float inv0 = 1.f / l0, inv1 = 1.f / l1;
    int token0 = b * SEQ + qb * 64 + row0 + gid;
    __half* op0 = Oh + (size_t)token0 * HIDDEN + h * HD;
    __half* op1 = op0 + (size_t)8 * HIDDEN;
    #pragma unroll
    for (int nt = 0; nt < 8; nt++) {
        int col = nt * 8 + 2 * tid4;
        *(__half2*)(op0 + col) = __floats2half2_rn(o[nt][0] * inv0, o[nt][1] * inv0);
        *(__half2*)(op1 + col) = __floats2half2_rn(o[nt][2] * inv1, o[nt][3] * inv1);
    }
}

// ---------------------------------------------------------------------------
// Launch sequence
// ---------------------------------------------------------------------------
extern "C" void kernel_launch(void* const* d_in, const int* in_sizes, int n_in,
                              void* d_out, int out_size) {
    const float* x   = (const float*)d_in[0];
    const float* Wq  = (const float*)d_in[1];
    const float* Wk  = (const float*)d_in[2];
    const float* Wv  = (const float*)d_in[3];
    const float* Wo  = (const float*)d_in[4];
    const int*   pos = (const int*)d_in[5];
    float* out = (float*)d_out;

    __half *xh, *QKVh, *Oh, *Wqkv, *WtO;
    cudaGetSymbolAddress((void**)&xh,   g_xh);
    cudaGetSymbolAddress((void**)&QKVh, g_QKVh);
    cudaGetSymbolAddress((void**)&Oh,   g_Oh);
    cudaGetSymbolAddress((void**)&Wqkv, g_Wqkv);
    cudaGetSymbolAddress((void**)&WtO,  g_WtO);

    cudaFuncSetAttribute((const void*)gemm_h<true, true>,
                         cudaFuncAttributeMaxDynamicSharedMemorySize, GEMM_SMEM_BYTES);
    cudaFuncSetAttribute((const void*)gemm_h<false, false>,
                         cudaFuncAttributeMaxDynamicSharedMemorySize, GEMM_SMEM_BYTES);
    cudaFuncSetAttribute((const void*)flash_h,
                         cudaFuncAttributeMaxDynamicSharedMemorySize, FLASH_SMEM);

    const int M = BSTOK;        // 4096
    dim3 tb(32, 8);

    convert_x<<<(BSTOK * HIDDEN / 4 + 255) / 256, 256>>>(x, xh, BSTOK * HIDDEN / 4);
    transpose_kh<<<dim3(HIDDEN / 32, HIDDEN / 32), tb>>>(Wq, Wqkv, HIDDEN, HIDDEN);
    transpose_kh<<<dim3((NKV * HD) / 32, HIDDEN / 32), tb>>>(
        Wk, Wqkv + (size_t)KOFF * HIDDEN, HIDDEN, NKV * HD);
    transpose_kh<<<dim3((NKV * HD) / 32, HIDDEN / 32), tb>>>(
        Wv, Wqkv + (size_t)VOFF * HIDDEN, HIDDEN, NKV * HD);
    rope_table<<<(BSTOK * 32 + 255) / 256, 256>>>(pos);

    // fused QKV projection with in-epilogue RoPE
    gemm_h<true, true><<<dim3(QKVS / 128, M / 128), 256, GEMM_SMEM_BYTES>>>(
        xh, Wqkv, QKVh, M, QKVS, HIDDEN);

    flash_h<<<dim3(SEQ / 64, NH, BB), 128, FLASH_SMEM>>>(QKVh, Oh);

    transpose_kh<<<dim3(HIDDEN / 32, HIDDEN / 32), tb>>>(Wo, WtO, HIDDEN, HIDDEN);
    gemm_h<false, false><<<dim3(HIDDEN / 128, M / 128), 256, GEMM_SMEM_BYTES>>>(
        Oh, WtO, out, M, HIDDEN, HIDDEN);
}

// round 15
// speedup vs baseline: 1.4100x; 1.0201x over previous
#include <cuda_runtime.h>
#include <cuda_fp16.h>
#include <math.h>
#include <stdint.h>

#define HIDDEN 2048
#define NH 32
#define NKV 8
#define HD 64
#define BB 2
#define SEQ 2048
#define BSTOK (BB*SEQ)
#define QKVS 3072          // fused QKV row stride (halfs)
#define KOFF 2048
#define VOFF 2560

// ---------------------------------------------------------------------------
// Scratch
// ---------------------------------------------------------------------------
__device__ __half g_xh  [(size_t)BSTOK * HIDDEN];
__device__ __half g_QKVh[(size_t)BSTOK * QKVS];
__device__ __half g_Oh  [(size_t)BSTOK * HIDDEN];
__device__ __half g_Wqkv[(size_t)QKVS * HIDDEN];
__device__ __half g_WtO [(size_t)HIDDEN * HIDDEN];
__device__ float  g_cos[BSTOK * 32];
__device__ float  g_sin[BSTOK * 32];

// ---------------------------------------------------------------------------
// Helpers
// ---------------------------------------------------------------------------
__device__ __forceinline__ uint32_t smem_u32(const void* p) {
    uint32_t a;
    asm("{ .reg .u64 t; cvta.to.shared.u64 t, %1; cvt.u32.u64 %0, t; }"
        : "=r"(a) : "l"(p));
    return a;
}
__device__ __forceinline__ void cp16(uint32_t dst, const void* src) {
    asm volatile("cp.async.cg.shared.global [%0], [%1], 16;"
                 :: "r"(dst), "l"(src));
}
__device__ __forceinline__ void cp_commit() {
    asm volatile("cp.async.commit_group;");
}
__device__ __forceinline__ void ldsm4(uint32_t* r, uint32_t addr) {
    asm volatile("ldmatrix.sync.aligned.m8n8.x4.shared.b16 {%0,%1,%2,%3}, [%4];"
                 : "=r"(r[0]), "=r"(r[1]), "=r"(r[2]), "=r"(r[3]) : "r"(addr));
}
__device__ __forceinline__ void ldsm4t(uint32_t* r, uint32_t addr) {
    asm volatile("ldmatrix.sync.aligned.m8n8.x4.trans.shared.b16 {%0,%1,%2,%3}, [%4];"
                 : "=r"(r[0]), "=r"(r[1]), "=r"(r[2]), "=r"(r[3]) : "r"(addr));
}
__device__ __forceinline__ void mma16(float* c, const uint32_t* a,
                                      uint32_t b0, uint32_t b1) {
    asm volatile(
        "mma.sync.aligned.m16n8k16.row.col.f32.f16.f16.f32 "
        "{%0,%1,%2,%3}, {%4,%5,%6,%7}, {%8,%9}, {%0,%1,%2,%3};"
        : "+f"(c[0]), "+f"(c[1]), "+f"(c[2]), "+f"(c[3])
        : "r"(a[0]), "r"(a[1]), "r"(a[2]), "r"(a[3]), "r"(b0), "r"(b1));
}

// ---------------------------------------------------------------------------
// fp16 mma GEMM, cp.async 3-stage pipeline, K-chunk 64, 8-warp CTA,
// warp grid 4M x 2N (warp tile 32x64 -> one head per warp N-span).
// Fused RoPE + 1/sqrt(d) Q-scale in the epilogue for the QKV GEMM.
// C[M,N] = A[M,K] @ Bt[N,K]^T.  CTA tile 128x128.
// ---------------------------------------------------------------------------
#define KSTG 72
#define CHUNKB (128 * KSTG * 2)       // 18432 B per matrix per chunk
#define STAGEB (2 * CHUNKB)           // 36864
#define GEMM_SMEM_BYTES (3 * STAGEB)  // 110592

template<bool HOUT, bool ROPE>
__global__ __launch_bounds__(256, 1) void gemm_h(
    const __half* __restrict__ A, const __half* __restrict__ Bt,
    void* __restrict__ Cv, int M, int N, int K) {
    extern __shared__ __half sh[];
    const uint32_t sbase = smem_u32(sh);
    const int tid  = threadIdx.x;
    const int wid  = tid >> 5;
    const int lane = tid & 31;
    const int gid  = lane >> 2;
    const int tid4 = lane & 3;
    const int wm   = wid & 3;         // 0..3 (32 M-rows each)
    const int wn   = wid >> 2;        // 0..1 (64 N-cols each)
    const int m0 = blockIdx.y * 128;
    const int n0 = blockIdx.x * 128;

    const int arow = (lane & 7) + ((lane >> 3) & 1) * 8;
    const int akof = (lane >> 4) * 8;
    const int brow = (lane & 7) + (lane >> 4) * 8;
    const int bkof = ((lane >> 3) & 1) * 8;

    int lrow[4], lv[4];
    #pragma unroll
    for (int i = 0; i < 4; i++) {
        int lin = i * 256 + tid;
        lrow[i] = lin >> 3;
        lv[i]   = lin & 7;
    }

    const __half* Ag = A  + (size_t)m0 * K;
    const __half* Bg = Bt + (size_t)n0 * K;
    const int nch = K / 64;

    float acc[2][8][4];
    #pragma unroll
    for (int mt = 0; mt < 2; mt++)
        #pragma unroll
        for (int nt = 0; nt < 8; nt++)
            #pragma unroll
            for (int c = 0; c < 4; c++) acc[mt][nt][c] = 0.f;

    auto issue = [&](int ch) {
        uint32_t As = sbase + (ch % 3) * STAGEB;
        uint32_t Bs = As + CHUNKB;
        const __half* Agc = Ag + ch * 64;
        const __half* Bgc = Bg + ch * 64;
        #pragma unroll
        for (int i = 0; i < 4; i++) {
            uint32_t so = (uint32_t)(lrow[i] * KSTG + lv[i] * 8) * 2;
            cp16(As + so, Agc + (size_t)lrow[i] * K + lv[i] * 8);
            cp16(Bs + so, Bgc + (size_t)lrow[i] * K + lv[i] * 8);
        }
        cp_commit();
    };

    issue(0); issue(1); issue(2);

    for (int ch = 0; ch < nch; ch++) {
        asm volatile("cp.async.wait_group 2;");
        __syncthreads();

        const uint32_t As = sbase + (ch % 3) * STAGEB;
        const uint32_t Bs = As + CHUNKB;
        #pragma unroll
        for (int ks = 0; ks < 4; ks++) {
            uint32_t af[2][4], bf[8][2];
            #pragma unroll
            for (int mt = 0; mt < 2; mt++)
                ldsm4(af[mt], As + ((wm * 32 + mt * 16 + arow) * KSTG
                                    + ks * 16 + akof) * 2);
            #pragma unroll
            for (int p = 0; p < 4; p++) {
                uint32_t b4[4];
                ldsm4(b4, Bs + ((wn * 64 + p * 16 + brow) * KSTG
                                + ks * 16 + bkof) * 2);
                bf[2 * p][0] = b4[0]; bf[2 * p][1] = b4[1];
                bf[2 * p + 1][0] = b4[2]; bf[2 * p + 1][1] = b4[3];
            }
            #pragma unroll
            for (int mt = 0; mt < 2; mt++)
                #pragma unroll
                for (int nt = 0; nt < 8; nt++)
                    mma16(acc[mt][nt], af[mt], bf[nt][0], bf[nt][1]);
        }
        __syncthreads();

        if (ch + 3 < nch) issue(ch + 3);
        else cp_commit();          // empty group keeps wait arithmetic exact
    }

    // Epilogue. Warp N-span = 64 = one head; pairs (i, i+32) are
    // acc[.][nt] / acc[.][nt+4]. QKV GEMM: rope Q+K, scale Q by 1/8.
    const bool do_rope  = ROPE && (n0 < VOFF);
    const bool do_scale = ROPE && (n0 < KOFF);
    #pragma unroll
    for (int mt = 0; mt < 2; mt++) {
        const int r = m0 + wm * 32 + mt * 16 + gid;     // rows r, r+8
        if (do_rope) {
            #pragma unroll
            for (int nt = 0; nt < 4; nt++) {
                const int i = nt * 8 + tid4 * 2;
                float2 c0 = *(const float2*)&g_cos[(size_t)r * 32 + i];
                float2 s0 = *(const float2*)&g_sin[(size_t)r * 32 + i];
                float2 c1 = *(const float2*)&g_cos[(size_t)(r + 8) * 32 + i];
                float2 s1 = *(const float2*)&g_sin[(size_t)(r + 8) * 32 + i];
                float x1, x2;
                x1 = acc[mt][nt][0]; x2 = acc[mt][nt + 4][0];
                acc[mt][nt][0]     = x1 * c0.x - x2 * s0.x;
                acc[mt][nt + 4][0] = x2 * c0.x + x1 * s0.x;
                x1 = acc[mt][nt][1]; x2 = acc[mt][nt + 4][1];
                acc[mt][nt][1]     = x1 * c0.y - x2 * s0.y;
                acc[mt][nt + 4][1] = x2 * c0.y + x1 * s0.y;
                x1 = acc[mt][nt][2]; x2 = acc[mt][nt + 4][2];
                acc[mt][nt][2]     = x1 * c1.x - x2 * s1.x;
                acc[mt][nt + 4][2] = x2 * c1.x + x1 * s1.x;
                x1 = acc[mt][nt][3]; x2 = acc[mt][nt + 4][3];
                acc[mt][nt][3]     = x1 * c1.y - x2 * s1.y;
                acc[mt][nt + 4][3] = x2 * c1.y + x1 * s1.y;
            }
        }
        if (do_scale) {
            #pragma unroll
            for (int nt = 0; nt < 8; nt++)
                #pragma unroll
                for (int c = 0; c < 4; c++) acc[mt][nt][c] *= 0.125f;
        }
        #pragma unroll
        for (int nt = 0; nt < 8; nt++) {
            const int col = n0 + wn * 64 + nt * 8 + tid4 * 2;
            if (HOUT) {
                __half* C = (__half*)Cv;
                *(__half2*)(C + (size_t)r * N + col) =
                    __floats2half2_rn(acc[mt][nt][0], acc[mt][nt][1]);
                *(__half2*)(C + (size_t)(r + 8) * N + col) =
                    __floats2half2_rn(acc[mt][nt][2], acc[mt][nt][3]);
            } else {
                float* C = (float*)Cv;
                float2 v0 = { acc[mt][nt][0], acc[mt][nt][1] };
                float2 v1 = { acc[mt][nt][2], acc[mt][nt][3] };
                *(float2*)(C + (size_t)r * N + col)       = v0;
                *(float2*)(C + (size_t)(r + 8) * N + col) = v1;
            }
        }
    }
}

// ---------------------------------------------------------------------------
// prep_all: one launch doing all 4 weight transposes, x->half convert,
// and the fp64 rope table. Block-range dispatch; branches are uniform
// per block so __syncthreads stays legal.
// ---------------------------------------------------------------------------
#define TB_TRQ 4096                    // Wq: (2048/32) x (2048/32)
#define TB_TRK 1024                    // Wk: (512/32) x (2048/32)
#define TB_TRV 1024
#define TB_TRO 4096
#define TB_CVT 8192                    // 2M float4 / 256
#define TB_RT  512                     // 131072 / 256
#define TB_TOTAL (TB_TRQ + TB_TRK + TB_TRV + TB_TRO + TB_CVT + TB_RT)

__global__ __launch_bounds__(256) void prep_all(
    const float* __restrict__ x,
    const float* __restrict__ Wq, const float* __restrict__ Wk,
    const float* __restrict__ Wv, const float* __restrict__ Wo,
    const int* __restrict__ pos,
    __half* __restrict__ xh, __half* __restrict__ Wqkv,
    __half* __restrict__ WtO) {
    __shared__ float tile[32][33];
    const int blk = blockIdx.x;
    const int tid = threadIdx.x;

    if (blk < TB_TRQ + TB_TRK + TB_TRV + TB_TRO) {
        const float* W; __half* Wt; int R, C, bx, by;
        if (blk < TB_TRQ) {
            W = Wq; Wt = Wqkv; R = HIDDEN; C = HIDDEN;
            bx = blk & 63; by = blk >> 6;
        } else if (blk < TB_TRQ + TB_TRK) {
            int l = blk - TB_TRQ;
            W = Wk; Wt = Wqkv + (size_t)KOFF * HIDDEN; R = HIDDEN; C = NKV * HD;
            bx = l & 15; by = l >> 4;
        } else if (blk < TB_TRQ + TB_TRK + TB_TRV) {
            int l = blk - TB_TRQ - TB_TRK;
            W = Wv; Wt = Wqkv + (size_t)VOFF * HIDDEN; R = HIDDEN; C = NKV * HD;
            bx = l & 15; by = l >> 4;
        } else {
            int l = blk - TB_TRQ - TB_TRK - TB_TRV;
            W = Wo; Wt = WtO; R = HIDDEN; C = HIDDEN;
            bx = l & 63; by = l >> 6;
        }
        const int tx = tid & 31, ty = tid >> 5;        // 32 x 8
        const int c0 = bx * 32, r0 = by * 32;
        #pragma unroll
        for (int j = ty; j < 32; j += 8)
            tile[j][tx] = W[(size_t)(r0 + j) * C + c0 + tx];
        __syncthreads();
        #pragma unroll
        for (int j = ty; j < 32; j += 8)
            Wt[(size_t)(c0 + j) * R + r0 + tx] = __float2half_rn(tile[tx][j]);
    } else if (blk < TB_TOTAL - TB_RT) {
        int idx = (blk - (TB_TRQ + TB_TRK + TB_TRV + TB_TRO)) * 256 + tid;
        float4 v = ((const float4*)x)[idx];
        ((__half2*)xh)[2 * idx]     = __floats2half2_rn(v.x, v.y);
        ((__half2*)xh)[2 * idx + 1] = __floats2half2_rn(v.z, v.w);
    } else {
        int idx = (blk - (TB_TOTAL - TB_RT)) * 256 + tid;
        int i = idx & 31, bs = idx >> 5;
        double inv_freq = exp(-(double)i * (9.210340371976184 / 32.0));
        double a = (double)pos[bs] * inv_freq;
        double s, c;
        sincos(a, &s, &c);
        g_cos[idx] = (float)c;
        g_sin[idx] = (float)s;
    }
}

// ---------------------------------------------------------------------------
// fp16 flash attention: 64-query CTA, cp.async double-buffered K/V,
// heavy CTAs first. Q pre-scaled by 1/sqrt(d) in the QKV epilogue.
// ---------------------------------------------------------------------------
#define KSTH 72
#define KVT (64 * KSTH)
#define FLASH_SMEM (5 * KVT * 2)   // 46080 B

__global__ __launch_bounds__(128, 1) void flash_h(
    const __half* __restrict__ QKV, __half* __restrict__ Oh) {
    extern __shared__ __half fsh[];
    const uint32_t fbase = smem_u32(fsh);
    __half* Ss = fsh + 4 * KVT;
    const uint32_t ssb = fbase + 4 * KVT * 2;

    const int tid  = threadIdx.x;
    const int warp = tid >> 5;
    const int lane = tid & 31;
    const int gid  = lane >> 2;
    const int tid4 = lane & 3;
    const int qb = gridDim.x - 1 - blockIdx.x;
    const int h = blockIdx.y, b = blockIdx.z;
    const int hkv = h >> 2;
    const int row0 = warp * 16;

    const int arow = (lane & 7) + ((lane >> 3) & 1) * 8;
    const int akof = (lane >> 4) * 8;
    const int brow = (lane & 7) + (lane >> 4) * 8;
    const int bkof = ((lane >> 3) & 1) * 8;
    const int vrow = (lane & 7) + ((lane >> 3) & 1) * 8;
    const int vkof = (lane >> 4) * 8;

    int klin[4], kv_[4];
    #pragma unroll
    for (int i = 0; i < 4; i++) {
        int lin = i * 128 + tid;
        klin[i] = lin >> 3;
        kv_[i]  = lin & 7;
    }
    auto issue = [&](int kt) {
        uint32_t Kb = fbase + (kt & 1) * 2 * KVT * 2;
        uint32_t Vb = Kb + KVT * 2;
        #pragma unroll
        for (int i = 0; i < 4; i++) {
            size_t rowb = (size_t)(b * SEQ + kt * 64 + klin[i]) * QKVS
                          + hkv * HD + kv_[i] * 8;
            uint32_t so = (uint32_t)(klin[i] * KSTH + kv_[i] * 8) * 2;
            cp16(Kb + so, QKV + rowb + KOFF);
            cp16(Vb + so, QKV + rowb + VOFF);
        }
        cp_commit();
    };

    #pragma unroll
    for (int j = 0; j < 4; j++) {
        int idx = j * 32 + lane;
        int r = idx >> 3, v = idx & 7;
        int token = b * SEQ + qb * 64 + row0 + r;
        *(uint4*)(Ss + (row0 + r) * KSTH + v * 8) =
            *(const uint4*)(QKV + (size_t)token * QKVS + h * HD + v * 8);
    }
    __syncwarp();
    uint32_t qf[4][4];
    #pragma unroll
    for (int ks = 0; ks < 4; ks++)
        ldsm4(qf[ks], ssb + ((row0 + arow) * KSTH + ks * 16 + akof) * 2);
    __syncwarp();

    float o[8][4];
    #pragma unroll
    for (int nt = 0; nt < 8; nt++)
        #pragma unroll
        for (int i = 0; i < 4; i++) o[nt][i] = 0.f;
    float m0 = -1e30f, m1 = -1e30f, l0 = 0.f, l1 = 0.f;

    issue(0);

    for (int kt = 0; kt <= qb; kt++) {
        if (kt < qb) { issue(kt + 1); asm volatile("cp.async.wait_group 1;"); }
        else         {                asm volatile("cp.async.wait_group 0;"); }
        __syncthreads();

        const uint32_t ksb = fbase + (kt & 1) * 2 * KVT * 2;
        const uint32_t vsb = ksb + KVT * 2;

        float c[8][4];
        #pragma unroll
        for (int nt = 0; nt < 8; nt++)
            #pragma unroll
            for (int i = 0; i < 4; i++) c[nt][i] = 0.f;
        #pragma unroll
        for (int ks = 0; ks < 4; ks++)
            #pragma unroll
            for (int p = 0; p < 4; p++) {
                uint32_t b4[4];
                ldsm4(b4, ksb + ((p * 16 + brow) * KSTH + ks * 16 + bkof) * 2);
                mma16(c[2 * p],     qf[ks], b4[0], b4[1]);
                mma16(c[2 * p + 1], qf[ks], b4[2], b4[3]);
            }

        // Q pre-scaled; straight to masking.
        if (kt == qb) {
            const int r0l = row0 + gid, r1l = row0 + gid + 8;
            #pragma unroll
            for (int nt = 0; nt < 8; nt++) {
                int cb = nt * 8 + 2 * tid4;
                if (cb     > r0l) c[nt][0] = -1e30f;
                if (cb + 1 > r0l) c[nt][1] = -1e30f;
                if (cb     > r1l) c[nt][2] = -1e30f;
                if (cb + 1 > r1l) c[nt][3] = -1e30f;
            }
        }

        float t0 = -1e30f, t1 = -1e30f;
        #pragma unroll
        for (int nt = 0; nt < 8; nt++) {
            t0 = fmaxf(t0, fmaxf(c[nt][0], c[nt][1]));
            t1 = fmaxf(t1, fmaxf(c[nt][2], c[nt][3]));
        }
        t0 = fmaxf(t0, __shfl_xor_sync(0xffffffffu, t0, 1));
        t0 = fmaxf(t0, __shfl_xor_sync(0xffffffffu, t0, 2));
        t1 = fmaxf(t1, __shfl_xor_sync(0xffffffffu, t1, 1));
        t1 = fmaxf(t1, __shfl_xor_sync(0xffffffffu, t1, 2));
        float m0n = fmaxf(m0, t0);
        float m1n = fmaxf(m1, t1);
        float cor0 = __expf(m0 - m0n);
        float cor1 = __expf(m1 - m1n);
        #pragma unroll
        for (int nt = 0; nt < 8; nt++) {
            o[nt][0] *= cor0; o[nt][1] *= cor0;
            o[nt][2] *= cor1; o[nt][3] *= cor1;
        }

        float s0 = 0.f, s1 = 0.f;
        #pragma unroll
        for (int nt = 0; nt < 8; nt++) {
            float p0 = __expf(c[nt][0] - m0n);
            float p1 = __expf(c[nt][1] - m0n);
            float p2 = __expf(c[nt][2] - m1n);
            float p3 = __expf(c[nt][3] - m1n);
            s0 += p0 + p1;
            s1 += p2 + p3;
            *(__half2*)(Ss + (row0 + gid)     * KSTH + nt * 8 + 2 * tid4) =
                __floats2half2_rn(p0, p1);
            *(__half2*)(Ss + (row0 + gid + 8) * KSTH + nt * 8 + 2 * tid4) =
                __floats2half2_rn(p2, p3);
        }
        s0 += __shfl_xor_sync(0xffffffffu, s0, 1);
        s0 += __shfl_xor_sync(0xffffffffu, s0, 2);
        s1 += __shfl_xor_sync(0xffffffffu, s1, 1);
        s1 += __shfl_xor_sync(0xffffffffu, s1, 2);
        l0 = l0 * cor0 + s0;
        l1 = l1 * cor1 + s1;
        m0 = m0n; m1 = m1n;
        __syncwarp();

        #pragma unroll
        for (int ks = 0; ks < 4; ks++) {
            uint32_t a4[4];
            ldsm4(a4, ssb + ((row0 + arow) * KSTH + ks * 16 + akof) * 2);
            #pragma unroll
            for (int p = 0; p < 4; p++) {
                uint32_t b4[4];
                ldsm4t(b4, vsb + ((ks * 16 + vrow) * KSTH + p * 16 + vkof) * 2);
                mma16(o[2 * p],     a4, b4[0], b4[1]);
                mma16(o[2 * p + 1], a4, b4[2], b4[3]);
            }
        }
        __syncthreads();
    }

    float inv0 = 1.f / l0, inv1 = 1.f / l1;
    int token0 = b * SEQ + qb * 64 + row0 + gid;
    __half* op0 = Oh + (size_t)token0 * HIDDEN + h * HD;
    __half* op1 = op0 + (size_t)8 * HIDDEN;
    #pragma unroll
    for (int nt = 0; nt < 8; nt++) {
        int col = nt * 8 + 2 * tid4;
        *(__half2*)(op0 + col) = __floats2half2_rn(o[nt][0] * inv0, o[nt][1] * inv0);
        *(__half2*)(op1 + col) = __floats2half2_rn(o[nt][2] * inv1, o[nt][3] * inv1);
    }
}

// ---------------------------------------------------------------------------
// Launch sequence: 4 launches total
// ---------------------------------------------------------------------------
extern "C" void kernel_launch(void* const* d_in, const int* in_sizes, int n_in,
                              void* d_out, int out_size) {
    const float* x   = (const float*)d_in[0];
    const float* Wq  = (const float*)d_in[1];
    const float* Wk  = (const float*)d_in[2];
    const float* Wv  = (const float*)d_in[3];
    const float* Wo  = (const float*)d_in[4];
    const int*   pos = (const int*)d_in[5];
    float* out = (float*)d_out;

    __half *xh, *QKVh, *Oh, *Wqkv, *WtO;
    cudaGetSymbolAddress((void**)&xh,   g_xh);
    cudaGetSymbolAddress((void**)&QKVh, g_QKVh);
    cudaGetSymbolAddress((void**)&Oh,   g_Oh);
    cudaGetSymbolAddress((void**)&Wqkv, g_Wqkv);
    cudaGetSymbolAddress((void**)&WtO,  g_WtO);

    cudaFuncSetAttribute((const void*)gemm_h<true, true>,
                         cudaFuncAttributeMaxDynamicSharedMemorySize, GEMM_SMEM_BYTES);
    cudaFuncSetAttribute((const void*)gemm_h<false, false>,
                         cudaFuncAttributeMaxDynamicSharedMemorySize, GEMM_SMEM_BYTES);
    cudaFuncSetAttribute((const void*)flash_h,
                         cudaFuncAttributeMaxDynamicSharedMemorySize, FLASH_SMEM);

    const int M = BSTOK;        // 4096

    // 1: all prep work in one launch
    prep_all<<<TB_TOTAL, 256>>>(x, Wq, Wk, Wv, Wo, pos, xh, Wqkv, WtO);

    // 2: fused QKV projection with in-epilogue RoPE + Q-scale
    gemm_h<true, true><<<dim3(QKVS / 128, M / 128), 256, GEMM_SMEM_BYTES>>>(
        xh, Wqkv, QKVh, M, QKVS, HIDDEN);

    // 3: flash attention
    flash_h<<<dim3(SEQ / 64, NH, BB), 128, FLASH_SMEM>>>(QKVh, Oh);

    // 4: output projection
    gemm_h<false, false><<<dim3(HIDDEN / 128, M / 128), 256, GEMM_SMEM_BYTES>>>(
        Oh, WtO, out, M, HIDDEN, HIDDEN);
}

// round 17
// speedup vs baseline: 1.6371x; 1.1611x over previous
#include <cuda_runtime.h>
#include <cuda_fp16.h>
#include <math.h>
#include <stdint.h>

#define HIDDEN 2048
#define NH 32
#define NKV 8
#define HD 64
#define BB 2
#define SEQ 2048
#define BSTOK (BB*SEQ)
#define QKVS 3072          // fused QKV row stride (halfs)
#define KOFF 2048
#define VOFF 2560

// ---------------------------------------------------------------------------
// Scratch
// ---------------------------------------------------------------------------
__device__ __half g_xh  [(size_t)BSTOK * HIDDEN];
__device__ __half g_QKVh[(size_t)BSTOK * QKVS];
__device__ __half g_Oh  [(size_t)BSTOK * HIDDEN];
__device__ __half g_Wqkv[(size_t)QKVS * HIDDEN];
__device__ __half g_WtO [(size_t)HIDDEN * HIDDEN];
__device__ float  g_cos[BSTOK * 32];
__device__ float  g_sin[BSTOK * 32];

// ---------------------------------------------------------------------------
// Helpers
// ---------------------------------------------------------------------------
__device__ __forceinline__ uint32_t smem_u32(const void* p) {
    uint32_t a;
    asm("{ .reg .u64 t; cvta.to.shared.u64 t, %1; cvt.u32.u64 %0, t; }"
        : "=r"(a) : "l"(p));
    return a;
}
__device__ __forceinline__ void cp16(uint32_t dst, const void* src) {
    asm volatile("cp.async.cg.shared.global [%0], [%1], 16;"
                 :: "r"(dst), "l"(src));
}
__device__ __forceinline__ void cp_commit() {
    asm volatile("cp.async.commit_group;");
}
__device__ __forceinline__ void ldsm4(uint32_t* r, uint32_t addr) {
    asm volatile("ldmatrix.sync.aligned.m8n8.x4.shared.b16 {%0,%1,%2,%3}, [%4];"
                 : "=r"(r[0]), "=r"(r[1]), "=r"(r[2]), "=r"(r[3]) : "r"(addr));
}
__device__ __forceinline__ void ldsm4t(uint32_t* r, uint32_t addr) {
    asm volatile("ldmatrix.sync.aligned.m8n8.x4.trans.shared.b16 {%0,%1,%2,%3}, [%4];"
                 : "=r"(r[0]), "=r"(r[1]), "=r"(r[2]), "=r"(r[3]) : "r"(addr));
}
__device__ __forceinline__ void mma16(float* c, const uint32_t* a,
                                      uint32_t b0, uint32_t b1) {
    asm volatile(
        "mma.sync.aligned.m16n8k16.row.col.f32.f16.f16.f32 "
        "{%0,%1,%2,%3}, {%4,%5,%6,%7}, {%8,%9}, {%0,%1,%2,%3};"
        : "+f"(c[0]), "+f"(c[1]), "+f"(c[2]), "+f"(c[3])
        : "r"(a[0]), "r"(a[1]), "r"(a[2]), "r"(a[3]), "r"(b0), "r"(b1));
}

// ---------------------------------------------------------------------------
// fp16 mma GEMM, cp.async 3-stage pipeline, K-chunk 64, 8-warp CTA,
// warp grid 4M x 2N (warp tile 32x64). __launch_bounds__(256,2) caps regs
// at 128 -> 2 CTAs/SM (R15 ncu showed occ=12.5% at 156 regs).
// B fragments consumed immediately after each ldmatrix (short live ranges).
// Fused RoPE + 1/sqrt(d) Q-scale in the epilogue for the QKV GEMM.
// ---------------------------------------------------------------------------
#define KSTG 72
#define CHUNKB (128 * KSTG * 2)       // 18432 B per matrix per chunk
#define STAGEB (2 * CHUNKB)           // 36864
#define GEMM_SMEM_BYTES (3 * STAGEB)  // 110592

template<bool HOUT, bool ROPE>
__global__ __launch_bounds__(256, 2) void gemm_h(
    const __half* __restrict__ A, const __half* __restrict__ Bt,
    void* __restrict__ Cv, int M, int N, int K) {
    extern __shared__ __half sh[];
    const uint32_t sbase = smem_u32(sh);
    const int tid  = threadIdx.x;
    const int wid  = tid >> 5;
    const int lane = tid & 31;
    const int gid  = lane >> 2;
    const int tid4 = lane & 3;
    const int wm   = wid & 3;         // 0..3 (32 M-rows each)
    const int wn   = wid >> 2;        // 0..1 (64 N-cols each)
    const int m0 = blockIdx.y * 128;
    const int n0 = blockIdx.x * 128;

    const int arow = (lane & 7) + ((lane >> 3) & 1) * 8;
    const int akof = (lane >> 4) * 8;
    const int brow = (lane & 7) + (lane >> 4) * 8;
    const int bkof = ((lane >> 3) & 1) * 8;

    int lrow[4], lv[4];
    #pragma unroll
    for (int i = 0; i < 4; i++) {
        int lin = i * 256 + tid;
        lrow[i] = lin >> 3;
        lv[i]   = lin & 7;
    }

    const __half* Ag = A  + (size_t)m0 * K;
    const __half* Bg = Bt + (size_t)n0 * K;
    const int nch = K / 64;

    float acc[2][8][4];
    #pragma unroll
    for (int mt = 0; mt < 2; mt++)
        #pragma unroll
        for (int nt = 0; nt < 8; nt++)
            #pragma unroll
            for (int c = 0; c < 4; c++) acc[mt][nt][c] = 0.f;

    auto issue = [&](int ch) {
        uint32_t As = sbase + (ch % 3) * STAGEB;
        uint32_t Bs = As + CHUNKB;
        const __half* Agc = Ag + ch * 64;
        const __half* Bgc = Bg + ch * 64;
        #pragma unroll
        for (int i = 0; i < 4; i++) {
            uint32_t so = (uint32_t)(lrow[i] * KSTG + lv[i] * 8) * 2;
            cp16(As + so, Agc + (size_t)lrow[i] * K + lv[i] * 8);
            cp16(Bs + so, Bgc + (size_t)lrow[i] * K + lv[i] * 8);
        }
        cp_commit();
    };

    issue(0); issue(1); issue(2);

    for (int ch = 0; ch < nch; ch++) {
        asm volatile("cp.async.wait_group 2;");
        __syncthreads();

        const uint32_t As = sbase + (ch % 3) * STAGEB;
        const uint32_t Bs = As + CHUNKB;
        #pragma unroll
        for (int ks = 0; ks < 4; ks++) {
            uint32_t af[2][4];
            #pragma unroll
            for (int mt = 0; mt < 2; mt++)
                ldsm4(af[mt], As + ((wm * 32 + mt * 16 + arow) * KSTG
                                    + ks * 16 + akof) * 2);
            #pragma unroll
            for (int p = 0; p < 4; p++) {
                uint32_t b4[4];
                ldsm4(b4, Bs + ((wn * 64 + p * 16 + brow) * KSTG
                                + ks * 16 + bkof) * 2);
                #pragma unroll
                for (int mt = 0; mt < 2; mt++) {
                    mma16(acc[mt][2 * p],     af[mt], b4[0], b4[1]);
                    mma16(acc[mt][2 * p + 1], af[mt], b4[2], b4[3]);
                }
            }
        }
        __syncthreads();

        if (ch + 3 < nch) issue(ch + 3);
        else cp_commit();          // empty group keeps wait arithmetic exact
    }

    // Epilogue. Warp N-span = 64 = one head; pairs (i, i+32) are
    // acc[.][nt] / acc[.][nt+4]. QKV GEMM: rope Q+K, scale Q by 1/8.
    const bool do_rope  = ROPE && (n0 < VOFF);
    const bool do_scale = ROPE && (n0 < KOFF);
    #pragma unroll
    for (int mt = 0; mt < 2; mt++) {
        const int r = m0 + wm * 32 + mt * 16 + gid;     // rows r, r+8
        if (do_rope) {
            #pragma unroll
            for (int nt = 0; nt < 4; nt++) {
                const int i = nt * 8 + tid4 * 2;
                float2 c0 = *(const float2*)&g_cos[(size_t)r * 32 + i];
                float2 s0 = *(const float2*)&g_sin[(size_t)r * 32 + i];
                float2 c1 = *(const float2*)&g_cos[(size_t)(r + 8) * 32 + i];
                float2 s1 = *(const float2*)&g_sin[(size_t)(r + 8) * 32 + i];
                float x1, x2;
                x1 = acc[mt][nt][0]; x2 = acc[mt][nt + 4][0];
                acc[mt][nt][0]     = x1 * c0.x - x2 * s0.x;
                acc[mt][nt + 4][0] = x2 * c0.x + x1 * s0.x;
                x1 = acc[mt][nt][1]; x2 = acc[mt][nt + 4][1];
                acc[mt][nt][1]     = x1 * c0.y - x2 * s0.y;
                acc[mt][nt + 4][1] = x2 * c0.y + x1 * s0.y;
                x1 = acc[mt][nt][2]; x2 = acc[mt][nt + 4][2];
                acc[mt][nt][2]     = x1 * c1.x - x2 * s1.x;
                acc[mt][nt + 4][2] = x2 * c1.x + x1 * s1.x;
                x1 = acc[mt][nt][3]; x2 = acc[mt][nt + 4][3];
                acc[mt][nt][3]     = x1 * c1.y - x2 * s1.y;
                acc[mt][nt + 4][3] = x2 * c1.y + x1 * s1.y;
            }
        }
        if (do_scale) {
            #pragma unroll
            for (int nt = 0; nt < 8; nt++)
                #pragma unroll
                for (int c = 0; c < 4; c++) acc[mt][nt][c] *= 0.125f;
        }
        #pragma unroll
        for (int nt = 0; nt < 8; nt++) {
            const int col = n0 + wn * 64 + nt * 8 + tid4 * 2;
            if (HOUT) {
                __half* C = (__half*)Cv;
                *(__half2*)(C + (size_t)r * N + col) =
                    __floats2half2_rn(acc[mt][nt][0], acc[mt][nt][1]);
                *(__half2*)(C + (size_t)(r + 8) * N + col) =
                    __floats2half2_rn(acc[mt][nt][2], acc[mt][nt][3]);
            } else {
                float* C = (float*)Cv;
                float2 v0 = { acc[mt][nt][0], acc[mt][nt][1] };
                float2 v1 = { acc[mt][nt][2], acc[mt][nt][3] };
                *(float2*)(C + (size_t)r * N + col)       = v0;
                *(float2*)(C + (size_t)(r + 8) * N + col) = v1;
            }
        }
    }
}

// ---------------------------------------------------------------------------
// prep_all: one launch doing all 4 weight transposes, x->half convert,
// and the fp64 rope table. Block-range dispatch.
// ---------------------------------------------------------------------------
#define TB_TRQ 4096
#define TB_TRK 1024
#define TB_TRV 1024
#define TB_TRO 4096
#define TB_CVT 8192
#define TB_RT  512
#define TB_TOTAL (TB_TRQ + TB_TRK + TB_TRV + TB_TRO + TB_CVT + TB_RT)

__global__ __launch_bounds__(256) void prep_all(
    const float* __restrict__ x,
    const float* __restrict__ Wq, const float* __restrict__ Wk,
    const float* __restrict__ Wv, const float* __restrict__ Wo,
    const int* __restrict__ pos,
    __half* __restrict__ xh, __half* __restrict__ Wqkv,
    __half* __restrict__ WtO) {
    __shared__ float tile[32][33];
    const int blk = blockIdx.x;
    const int tid = threadIdx.x;

    if (blk < TB_TRQ + TB_TRK + TB_TRV + TB_TRO) {
        const float* W; __half* Wt; int R, C, bx, by;
        if (blk < TB_TRQ) {
            W = Wq; Wt = Wqkv; R = HIDDEN; C = HIDDEN;
            bx = blk & 63; by = blk >> 6;
        } else if (blk < TB_TRQ + TB_TRK) {
            int l = blk - TB_TRQ;
            W = Wk; Wt = Wqkv + (size_t)KOFF * HIDDEN; R = HIDDEN; C = NKV * HD;
            bx = l & 15; by = l >> 4;
        } else if (blk < TB_TRQ + TB_TRK + TB_TRV) {
            int l = blk - TB_TRQ - TB_TRK;
            W = Wv; Wt = Wqkv + (size_t)VOFF * HIDDEN; R = HIDDEN; C = NKV * HD;
            bx = l & 15; by = l >> 4;
        } else {
            int l = blk - TB_TRQ - TB_TRK - TB_TRV;
            W = Wo; Wt = WtO; R = HIDDEN; C = HIDDEN;
            bx = l & 63; by = l >> 6;
        }
        const int tx = tid & 31, ty = tid >> 5;
        const int c0 = bx * 32, r0 = by * 32;
        #pragma unroll
        for (int j = ty; j < 32; j += 8)
            tile[j][tx] = W[(size_t)(r0 + j) * C + c0 + tx];
        __syncthreads();
        #pragma unroll
        for (int j = ty; j < 32; j += 8)
            Wt[(size_t)(c0 + j) * R + r0 + tx] = __float2half_rn(tile[tx][j]);
    } else if (blk < TB_TOTAL - TB_RT) {
        int idx = (blk - (TB_TRQ + TB_TRK + TB_TRV + TB_TRO)) * 256 + tid;
        float4 v = ((const float4*)x)[idx];
        ((__half2*)xh)[2 * idx]     = __floats2half2_rn(v.x, v.y);
        ((__half2*)xh)[2 * idx + 1] = __floats2half2_rn(v.z, v.w);
    } else {
        int idx = (blk - (TB_TOTAL - TB_RT)) * 256 + tid;
        int i = idx & 31, bs = idx >> 5;
        double inv_freq = exp(-(double)i * (9.210340371976184 / 32.0));
        double a = (double)pos[bs] * inv_freq;
        double s, c;
        sincos(a, &s, &c);
        g_cos[idx] = (float)c;
        g_sin[idx] = (float)s;
    }
}

// ---------------------------------------------------------------------------
// fp16 flash attention: 64-query CTA, cp.async double-buffered K/V,
// heavy CTAs first. Q pre-scaled by 1/sqrt(d).
// ---------------------------------------------------------------------------
#define KSTH 72
#define KVT (64 * KSTH)
#define FLASH_SMEM (5 * KVT * 2)   // 46080 B

__global__ __launch_bounds__(128, 1) void flash_h(
    const __half* __restrict__ QKV, __half* __restrict__ Oh) {
    extern __shared__ __half fsh[];
    const uint32_t fbase = smem_u32(fsh);
    __half* Ss = fsh + 4 * KVT;
    const uint32_t ssb = fbase + 4 * KVT * 2;

    const int tid  = threadIdx.x;
    const int warp = tid >> 5;
    const int lane = tid & 31;
    const int gid  = lane >> 2;
    const int tid4 = lane & 3;
    const int qb = gridDim.x - 1 - blockIdx.x;
    const int h = blockIdx.y, b = blockIdx.z;
    const int hkv = h >> 2;
    const int row0 = warp * 16;

    const int arow = (lane & 7) + ((lane >> 3) & 1) * 8;
    const int akof = (lane >> 4) * 8;
    const int brow = (lane & 7) + (lane >> 4) * 8;
    const int bkof = ((lane >> 3) & 1) * 8;
    const int vrow = (lane & 7) + ((lane >> 3) & 1) * 8;
    const int vkof = (lane >> 4) * 8;

    int klin[4], kv_[4];
    #pragma unroll
    for (int i = 0; i < 4; i++) {
        int lin = i * 128 + tid;
        klin[i] = lin >> 3;
        kv_[i]  = lin & 7;
    }
    auto issue = [&](int kt) {
        uint32_t Kb = fbase + (kt & 1) * 2 * KVT * 2;
        uint32_t Vb = Kb + KVT * 2;
        #pragma unroll
        for (int i = 0; i < 4; i++) {
            size_t rowb = (size_t)(b * SEQ + kt * 64 + klin[i]) * QKVS
                          + hkv * HD + kv_[i] * 8;
            uint32_t so = (uint32_t)(klin[i] * KSTH + kv_[i] * 8) * 2;
            cp16(Kb + so, QKV + rowb + KOFF);
            cp16(Vb + so, QKV + rowb + VOFF);
        }
        cp_commit();
    };

    #pragma unroll
    for (int j = 0; j < 4; j++) {
        int idx = j * 32 + lane;
        int r = idx >> 3, v = idx & 7;
        int token = b * SEQ + qb * 64 + row0 + r;
        *(uint4*)(Ss + (row0 + r) * KSTH + v * 8) =
            *(const uint4*)(QKV + (size_t)token * QKVS + h * HD + v * 8);
    }
    __syncwarp();
    uint32_t qf[4][4];
    #pragma unroll
    for (int ks = 0; ks < 4; ks++)
        ldsm4(qf[ks], ssb + ((row0 + arow) * KSTH + ks * 16 + akof) * 2);
    __syncwarp();

    float o[8][4];
    #pragma unroll
    for (int nt = 0; nt < 8; nt++)
        #pragma unroll
        for (int i = 0; i < 4; i++) o[nt][i] = 0.f;
    float m0 = -1e30f, m1 = -1e30f, l0 = 0.f, l1 = 0.f;

    issue(0);

    for (int kt = 0; kt <= qb; kt++) {
        if (kt < qb) { issue(kt + 1); asm volatile("cp.async.wait_group 1;"); }
        else         {                asm volatile("cp.async.wait_group 0;"); }
        __syncthreads();

        const uint32_t ksb = fbase + (kt & 1) * 2 * KVT * 2;
        const uint32_t vsb = ksb + KVT * 2;

        float c[8][4];
        #pragma unroll
        for (int nt = 0; nt < 8; nt++)
            #pragma unroll
            for (int i = 0; i < 4; i++) c[nt][i] = 0.f;
        #pragma unroll
        for (int ks = 0; ks < 4; ks++)
            #pragma unroll
            for (int p = 0; p < 4; p++) {
                uint32_t b4[4];
                ldsm4(b4, ksb + ((p * 16 + brow) * KSTH + ks * 16 + bkof) * 2);
                mma16(c[2 * p],     qf[ks], b4[0], b4[1]);
                mma16(c[2 * p + 1], qf[ks], b4[2], b4[3]);
            }

        if (kt == qb) {
            const int r0l = row0 + gid, r1l = row0 + gid + 8;
            #pragma unroll
            for (int nt = 0; nt < 8; nt++) {
                int cb = nt * 8 + 2 * tid4;
                if (cb     > r0l) c[nt][0] = -1e30f;
                if (cb + 1 > r0l) c[nt][1] = -1e30f;
                if (cb     > r1l) c[nt][2] = -1e30f;
                if (cb + 1 > r1l) c[nt][3] = -1e30f;
            }
        }

        float t0 = -1e30f, t1 = -1e30f;
        #pragma unroll
        for (int nt = 0; nt < 8; nt++) {
            t0 = fmaxf(t0, fmaxf(c[nt][0], c[nt][1]));
            t1 = fmaxf(t1, fmaxf(c[nt][2], c[nt][3]));
        }
        t0 = fmaxf(t0, __shfl_xor_sync(0xffffffffu, t0, 1));
        t0 = fmaxf(t0, __shfl_xor_sync(0xffffffffu, t0, 2));
        t1 = fmaxf(t1, __shfl_xor_sync(0xffffffffu, t1, 1));
        t1 = fmaxf(t1, __shfl_xor_sync(0xffffffffu, t1, 2));
        float m0n = fmaxf(m0, t0);
        float m1n = fmaxf(m1, t1);
        float cor0 = __expf(m0 - m0n);
        float cor1 = __expf(m1 - m1n);
        #pragma unroll
        for (int nt = 0; nt < 8; nt++) {
            o[nt][0] *= cor0; o[nt][1] *= cor0;
            o[nt][2] *= cor1; o[nt][3] *= cor1;
        }

        float s0 = 0.f, s1 = 0.f;
        #pragma unroll
        for (int nt = 0; nt < 8; nt++) {
            float p0 = __expf(c[nt][0] - m0n);
            float p1 = __expf(c[nt][1] - m0n);
            float p2 = __expf(c[nt][2] - m1n);
            float p3 = __expf(c[nt][3] - m1n);
            s0 += p0 + p1;
            s1 += p2 + p3;
            *(__half2*)(Ss + (row0 + gid)     * KSTH + nt * 8 + 2 * tid4) =
                __floats2half2_rn(p0, p1);
            *(__half2*)(Ss + (row0 + gid + 8) * KSTH + nt * 8 + 2 * tid4) =
                __floats2half2_rn(p2, p3);
        }
        s0 += __shfl_xor_sync(0xffffffffu, s0, 1);
        s0 += __shfl_xor_sync(0xffffffffu, s0, 2);
        s1 += __shfl_xor_sync(0xffffffffu, s1, 1);
        s1 += __shfl_xor_sync(0xffffffffu, s1, 2);
        l0 = l0 * cor0 + s0;
        l1 = l1 * cor1 + s1;
        m0 = m0n; m1 = m1n;
        __syncwarp();

        #pragma unroll
        for (int ks = 0; ks < 4; ks++) {
            uint32_t a4[4];
            ldsm4(a4, ssb + ((row0 + arow) * KSTH + ks * 16 + akof) * 2);
            #pragma unroll
            for (int p = 0; p < 4; p++) {
                uint32_t b4[4];
                ldsm4t(b4, vsb + ((ks * 16 + vrow) * KSTH + p * 16 + vkof) * 2);
                mma16(o[2 * p],     a4, b4[0], b4[1]);
                mma16(o[2 * p + 1], a4, b4[2], b4[3]);
            }
        }
        __syncthreads();
    }

    float inv0 = 1.f / l0, inv1 = 1.f / l1;
    int token0 = b * SEQ + qb * 64 + row0 + gid;
    __half* op0 = Oh + (size_t)token0 * HIDDEN + h * HD;
    __half* op1 = op0 + (size_t)8 * HIDDEN;
    #pragma unroll
    for (int nt = 0; nt < 8; nt++) {
        int col = nt * 8 + 2 * tid4;
        *(__half2*)(op0 + col) = __floats2half2_rn(o[nt][0] * inv0, o[nt][1] * inv0);
        *(__half2*)(op1 + col) = __floats2half2_rn(o[nt][2] * inv1, o[nt][3] * inv1);
    }
}

// ---------------------------------------------------------------------------
// Launch sequence: 4 launches
// ---------------------------------------------------------------------------
extern "C" void kernel_launch(void* const* d_in, const int* in_sizes, int n_in,
                              void* d_out, int out_size) {
    const float* x   = (const float*)d_in[0];
    const float* Wq  = (const float*)d_in[1];
    const float* Wk  = (const float*)d_in[2];
    const float* Wv  = (const float*)d_in[3];
    const float* Wo  = (const float*)d_in[4];
    const int*   pos = (const int*)d_in[5];
    float* out = (float*)d_out;

    __half *xh, *QKVh, *Oh, *Wqkv, *WtO;
    cudaGetSymbolAddress((void**)&xh,   g_xh);
    cudaGetSymbolAddress((void**)&QKVh, g_QKVh);
    cudaGetSymbolAddress((void**)&Oh,   g_Oh);
    cudaGetSymbolAddress((void**)&Wqkv, g_Wqkv);
    cudaGetSymbolAddress((void**)&WtO,  g_WtO);

    cudaFuncSetAttribute((const void*)gemm_h<true, true>,
                         cudaFuncAttributeMaxDynamicSharedMemorySize, GEMM_SMEM_BYTES);
    cudaFuncSetAttribute((const void*)gemm_h<false, false>,
                         cudaFuncAttributeMaxDynamicSharedMemorySize, GEMM_SMEM_BYTES);
    cudaFuncSetAttribute((const void*)flash_h,
                         cudaFuncAttributeMaxDynamicSharedMemorySize, FLASH_SMEM);

    const int M = BSTOK;        // 4096

    prep_all<<<TB_TOTAL, 256>>>(x, Wq, Wk, Wv, Wo, pos, xh, Wqkv, WtO);

    gemm_h<true, true><<<dim3(QKVS / 128, M / 128), 256, GEMM_SMEM_BYTES>>>(
        xh, Wqkv, QKVh, M, QKVS, HIDDEN);

    flash_h<<<dim3(SEQ / 64, NH, BB), 128, FLASH_SMEM>>>(QKVh, Oh);

    gemm_h<false, false><<<dim3(HIDDEN / 128, M / 128), 256, GEMM_SMEM_BYTES>>>(
        Oh, WtO, out, M, HIDDEN, HIDDEN);
}